// round 1
// baseline (speedup 1.0000x reference)
#include <cuda_runtime.h>
#include <math.h>
#include <math_constants.h>

#define H_ 512
#define W_ 1024
#define HW_ (H_*W_)
#define B_ 2
#define C_ 34
#define TOPK_ 200
#define MAXK_ 5888

// ---------------- scratch (device globals; no allocations allowed) ----------------
__device__ float g_vote[B_*HW_];
__device__ float g_m[B_*HW_];
__device__ float g_s[B_*HW_];
__device__ int   g_cnt[B_];
__device__ float g_kval[B_*MAXK_];
__device__ int   g_kidx[B_*MAXK_];
__device__ float g_ca[B_*TOPK_];
__device__ float g_cb[B_*TOPK_];
__device__ float g_cc[B_*TOPK_];
__device__ int   g_counts[B_*TOPK_*C_];
__device__ int   g_cls[B_*TOPK_];
__device__ float g_psum[B_*TOPK_];

// ---------------- K0: zero accumulators ----------------
__global__ void k_init() {
    int t = threadIdx.x;
    for (int i = t; i < B_*TOPK_*C_; i += blockDim.x) g_counts[i] = 0;
    for (int i = t; i < B_*TOPK_;    i += blockDim.x) g_psum[i] = 0.f;
    if (t < B_) g_cnt[t] = 0;
}

// ---------------- K1: argmax class + softmax max/denominator ----------------
__global__ __launch_bounds__(256) void k_seg(const float* __restrict__ logits,
                                             float* __restrict__ o_seg) {
    int pix = blockIdx.x * 256 + threadIdx.x;
    int b = blockIdx.y;
    const float* base = logits + (size_t)b * C_ * HW_ + pix;
    float v[C_];
    #pragma unroll
    for (int c = 0; c < C_; c++) v[c] = base[(size_t)c * HW_];
    float m = v[0]; int bi = 0;
    #pragma unroll
    for (int c = 1; c < C_; c++) if (v[c] > m) { m = v[c]; bi = c; }
    float s = 0.f;
    #pragma unroll
    for (int c = 0; c < C_; c++) s += expf(v[c] - m);
    int idx = b * HW_ + pix;
    o_seg[idx] = (float)bi;
    g_m[idx] = m;
    g_s[idx] = s;
}

// ---------------- K2: vote map (exact op order to match reference) ----------------
__global__ __launch_bounds__(256) void k_vote(const float* __restrict__ reg) {
    __shared__ float2 S[18][43];
    int b = blockIdx.z;
    int ox0 = blockIdx.x * 32, oy0 = blockIdx.y * 8;
    const float* r0 = reg + (size_t)b * 2 * HW_;
    const float* r1 = r0 + HW_;
    int tid = threadIdx.y * 32 + threadIdx.x;
    for (int t = tid; t < 18 * 42; t += 256) {
        int rr = t / 42, cc = t % 42;
        int gy = oy0 + rr - 5, gx = ox0 + cc - 5;
        float vx = 0.f, vy = 0.f;
        if (gy >= 0 && gy < H_ && gx >= 0 && gx < W_) {
            int q = gy * W_ + gx;
            vx = r0[q]; vy = r1[q];
        }
        S[rr][cc] = make_float2(vx, vy);
    }
    __syncthreads();
    int tx = threadIdx.x, ty = threadIdx.y;
    float acc = 0.f;
    #pragma unroll
    for (int i = 0; i < 11; i++) {
        #pragma unroll
        for (int j = 0; j < 11; j++) {
            const int di = i - 5, dj = j - 5;
            if (di*di + dj*dj <= 25) {   // cmask, compile-time
                float2 v = S[ty + i][tx + j];
                float dx = __fsub_rn((float)dj, v.x);
                float dy = __fsub_rn((float)di, v.y);
                float t2 = __fadd_rn(__fmul_rn(dx, dx), __fmul_rn(dy, dy));
                acc = __fadd_rn(acc, __fsqrt_rn(t2));
            }
        }
    }
    float t = __fdiv_rn(acc, 81.0f);
    float vote = __fadd_rn(-t, -1.0f);
    g_vote[b * HW_ + (oy0 + ty) * W_ + ox0 + tx] = vote;
}

// ---------------- K3: 7x7 max-pool + keep + center_map + keep list ----------------
__global__ __launch_bounds__(256) void k_pool(float thrF, float* __restrict__ o_cmap) {
    __shared__ float T[14][39];
    int b = blockIdx.z;
    int ox0 = blockIdx.x * 32, oy0 = blockIdx.y * 8;
    int tid = threadIdx.y * 32 + threadIdx.x;
    for (int t = tid; t < 14 * 38; t += 256) {
        int rr = t / 38, cc = t % 38;
        int gy = oy0 + rr - 3, gx = ox0 + cc - 3;
        T[rr][cc] = (gy >= 0 && gy < H_ && gx >= 0 && gx < W_)
                    ? g_vote[b * HW_ + gy * W_ + gx] : -CUDART_INF_F;
    }
    __syncthreads();
    int tx = threadIdx.x, ty = threadIdx.y;
    float v = T[ty + 3][tx + 3];
    float m = -CUDART_INF_F;
    #pragma unroll
    for (int i = 0; i < 7; i++)
        #pragma unroll
        for (int j = 0; j < 7; j++)
            m = fmaxf(m, T[ty + i][tx + j]);
    bool keep = (m == v) && (v > thrF);
    int pix = (oy0 + ty) * W_ + ox0 + tx;
    o_cmap[b * HW_ + pix] = keep ? v : 0.f;
    if (keep) {
        int p = atomicAdd(&g_cnt[b], 1);
        if (p < MAXK_) { g_kval[b * MAXK_ + p] = v; g_kidx[b * MAXK_ + p] = pix; }
    }
}

// ---------------- K4: exact top-200 (value desc, index asc; -inf fill) ----------------
__global__ __launch_bounds__(1024) void k_topk(const float* __restrict__ o_cmap,
                                               float* __restrict__ o_cent,
                                               float* __restrict__ o_tv) {
    __shared__ float sv[MAXK_];
    __shared__ int   si[MAXK_];
    __shared__ float tv[TOPK_];
    __shared__ int   ti[TOPK_];
    int b = blockIdx.x;
    int tid = threadIdx.x;
    int n = g_cnt[b];
    if (n > MAXK_) n = MAXK_;
    for (int i = tid; i < n; i += 1024) {
        sv[i] = g_kval[b * MAXK_ + i];
        si[i] = g_kidx[b * MAXK_ + i];
    }
    __syncthreads();
    for (int i = tid; i < n; i += 1024) {
        float v = sv[i]; int id = si[i];
        int r = 0;
        for (int j = 0; j < n; j++) {
            float vj = sv[j]; int ij = si[j];
            r += (vj > v) || (vj == v && ij < id);
        }
        if (r < TOPK_) { tv[r] = v; ti[r] = id; }
    }
    __syncthreads();
    if (tid == 0 && n < TOPK_) {
        // jax top_k pads with the lowest-index -inf entries (non-keep positions)
        const float* cm = o_cmap + (size_t)b * HW_;
        int slot = n;
        for (int idx = 0; idx < HW_ && slot < TOPK_; idx++) {
            if (cm[idx] == 0.f) { tv[slot] = -CUDART_INF_F; ti[slot] = idx; slot++; }
        }
    }
    __syncthreads();
    if (tid < TOPK_) {
        float v = tv[tid]; int id = ti[tid];
        int ys = id / W_, xs = id % W_;
        o_cent[(b * TOPK_ + tid) * 2 + 0] = (float)ys;
        o_cent[(b * TOPK_ + tid) * 2 + 1] = (float)xs;
        o_tv[b * TOPK_ + tid] = v;
        bool valid = isfinite(v);
        float cx = valid ? (float)xs : 1e9f;
        float cy = valid ? (float)ys : 1e9f;
        g_ca[b * TOPK_ + tid] = -2.f * cx;
        g_cb[b * TOPK_ + tid] = -2.f * cy;
        g_cc[b * TOPK_ + tid] = cx * cx + cy * cy;
    }
}

// ---------------- K5: nearest-center argmin -> inst_map ----------------
__global__ __launch_bounds__(256) void k_argmin(const float* __restrict__ reg,
                                                const float* __restrict__ o_seg,
                                                float* __restrict__ o_inst) {
    __shared__ float A[TOPK_], Bc[TOPK_], Cc[TOPK_];
    int b = blockIdx.y;
    int tid = threadIdx.x;
    if (tid < TOPK_) {
        A[tid]  = g_ca[b * TOPK_ + tid];
        Bc[tid] = g_cb[b * TOPK_ + tid];
        Cc[tid] = g_cc[b * TOPK_ + tid];
    }
    __syncthreads();
    int pix = blockIdx.x * 256 + tid;
    int y = pix >> 10, x = pix & 1023;
    const float* r0 = reg + (size_t)b * 2 * HW_;
    float px = (float)(x + 1) - r0[pix];
    float py = (float)(y + 1) - r0[HW_ + pix];
    float best = CUDART_INF_F; int bi = 0;
    #pragma unroll 10
    for (int k = 0; k < TOPK_; k++) {
        float t = __fmaf_rn(A[k], px, __fmaf_rn(Bc[k], py, Cc[k]));
        if (t < best) { best = t; bi = k; }
    }
    float s = o_seg[b * HW_ + pix];
    bool things = (s > 23.99f) && (s <= 33.0f);
    o_inst[b * HW_ + pix] = things ? (float)(bi + 1) : 0.f;
}

// ---------------- K6: per-instance class histogram ----------------
__global__ __launch_bounds__(256) void k_counts(const float* __restrict__ o_inst,
                                                const float* __restrict__ o_seg) {
    int pix = blockIdx.x * 256 + threadIdx.x;
    int b = blockIdx.y;
    int inst = (int)o_inst[b * HW_ + pix];
    if (inst > 0) {
        int cls = (int)o_seg[b * HW_ + pix];
        atomicAdd(&g_counts[(b * TOPK_ + inst - 1) * C_ + cls], 1);
    }
}

// ---------------- K7: instance class (argmax) + size ----------------
__global__ void k_class(float* __restrict__ o_cls, float* __restrict__ o_size) {
    int t = threadIdx.x;
    int b = blockIdx.x;
    const int* base = &g_counts[(b * TOPK_ + t) * C_];
    int sum = 0, best = -1, bi = 0;
    #pragma unroll
    for (int c = 0; c < C_; c++) {
        int cnt = base[c];
        sum += cnt;
        if (cnt > best) { best = cnt; bi = c; }
    }
    o_cls[b * TOPK_ + t]  = (float)bi;
    o_size[b * TOPK_ + t] = (float)sum;
    g_cls[b * TOPK_ + t]  = bi;
}

// ---------------- K8: per-instance prob sums (warp-aggregated atomics) ----------------
__global__ __launch_bounds__(256) void k_prob(const float* __restrict__ logits,
                                              const float* __restrict__ o_inst) {
    int pix = blockIdx.x * 256 + threadIdx.x;
    int b = blockIdx.y;
    int inst = (int)o_inst[b * HW_ + pix];
    float p = 0.f;
    if (inst > 0) {
        int c = g_cls[b * TOPK_ + inst - 1];
        int idx = b * HW_ + pix;
        float l = logits[((size_t)b * C_ + c) * HW_ + pix];
        p = expf(l - g_m[idx]) / g_s[idx];
    }
    unsigned peers = __match_any_sync(0xffffffffu, inst);
    int lane = threadIdx.x & 31;
    int leader = __ffs(peers) - 1;
    float tot = 0.f;
    #pragma unroll
    for (int k = 0; k < 32; k++) {
        float pk = __shfl_sync(0xffffffffu, p, k);
        if (peers & (1u << k)) tot += pk;
    }
    if (inst > 0 && lane == leader)
        atomicAdd(&g_psum[b * TOPK_ + inst - 1], tot);
}

// ---------------- K9: finalize inst_seg_prob ----------------
__global__ void k_fin(const float* __restrict__ o_size, float* __restrict__ o_prob) {
    int t = blockIdx.x * blockDim.x + threadIdx.x;
    if (t < B_ * TOPK_)
        o_prob[t] = g_psum[t] / fmaxf(o_size[t], 1.f);
}

// ---------------- host ----------------
extern "C" void kernel_launch(void* const* d_in, const int* in_sizes, int n_in,
                              void* d_out, int out_size) {
    const float* logits = (const float*)d_in[0];
    const float* regs   = (const float*)d_in[2];
    float* out = (float*)d_out;

    // Output layout (all float32, concatenated in tuple order)
    float* o_inst = out;                    // [B, H, W]
    float* o_seg  = out + 2 * HW_;          // [B, H, W]
    float* o_cent = out + 4 * HW_;          // [B, 200, 2]
    float* o_tv   = o_cent + B_ * TOPK_ * 2;// [B, 200]
    float* o_cls  = o_tv   + B_ * TOPK_;    // [B, 200]
    float* o_prob = o_cls  + B_ * TOPK_;    // [B, 200]
    float* o_size = o_prob + B_ * TOPK_;    // [B, 200]
    float* o_cmap = o_size + B_ * TOPK_;    // [B, H, W]

    // Threshold: replicate numpy float32 pairwise sum of (cd*cmask) over 11x11,
    // then thr = double(sum)/81.0, compare value = float(-thr - 1.0)
    float a[121];
    for (int i = 0; i < 11; i++)
        for (int j = 0; j < 11; j++) {
            int di = i - 5, dj = j - 5;
            int r2 = di * di + dj * dj;
            a[i * 11 + j] = (r2 <= 25) ? sqrtf((float)r2) : 0.0f;
        }
    float r[8];
    for (int k = 0; k < 8; k++) r[k] = a[k];
    int i = 8;
    for (; i < 120; i += 8)
        for (int k = 0; k < 8; k++) r[k] += a[i + k];
    float res = ((r[0] + r[1]) + (r[2] + r[3])) + ((r[4] + r[5]) + (r[6] + r[7]));
    for (; i < 121; i++) res += a[i];
    double thr = (double)res / 81.0;
    float thrF = (float)(-thr - 1.0);

    k_init<<<1, 1024>>>();
    k_seg<<<dim3(HW_ / 256, B_), 256>>>(logits, o_seg);
    k_vote<<<dim3(W_ / 32, H_ / 8, B_), dim3(32, 8)>>>(regs);
    k_pool<<<dim3(W_ / 32, H_ / 8, B_), dim3(32, 8)>>>(thrF, o_cmap);
    k_topk<<<B_, 1024>>>(o_cmap, o_cent, o_tv);
    k_argmin<<<dim3(HW_ / 256, B_), 256>>>(regs, o_seg, o_inst);
    k_counts<<<dim3(HW_ / 256, B_), 256>>>(o_inst, o_seg);
    k_class<<<B_, TOPK_>>>(o_cls, o_size);
    k_prob<<<dim3(HW_ / 256, B_), 256>>>(logits, o_inst);
    k_fin<<<1, 512>>>(o_size, o_prob);
}

// round 2
// speedup vs baseline: 2.7864x; 2.7864x over previous
#include <cuda_runtime.h>
#include <math.h>
#include <math_constants.h>

#define H_ 512
#define W_ 1024
#define HW_ (H_*W_)
#define B_ 2
#define C_ 34
#define TOPK_ 200
#define MAXK_ 5888

// ---------------- scratch (device globals; no allocations allowed) ----------------
__device__ float g_vote[B_*HW_];
__device__ float g_m[B_*HW_];
__device__ float g_s[B_*HW_];
__device__ int   g_cnt[B_];
__device__ float g_kval[B_*MAXK_];
__device__ int   g_kidx[B_*MAXK_];
__device__ float g_tv[B_*TOPK_];
__device__ int   g_ti[B_*TOPK_];
__device__ float g_ca[B_*TOPK_];
__device__ float g_cb[B_*TOPK_];
__device__ float g_cc[B_*TOPK_];
__device__ int   g_counts[B_*TOPK_*C_];
__device__ int   g_cls[B_*TOPK_];
__device__ float g_psum[B_*TOPK_];
__device__ int   g_tcnt[B_];
__device__ int   g_tlist[B_*HW_];

// ---------------- K0: zero accumulators ----------------
__global__ void k_init() {
    int t = threadIdx.x;
    for (int i = t; i < B_*TOPK_*C_; i += blockDim.x) g_counts[i] = 0;
    for (int i = t; i < B_*TOPK_;    i += blockDim.x) g_psum[i] = 0.f;
    if (t < B_) { g_cnt[t] = 0; g_tcnt[t] = 0; }
}

// ---------------- K1: argmax class + softmax max/denominator ----------------
__global__ __launch_bounds__(256) void k_seg(const float* __restrict__ logits,
                                             float* __restrict__ o_seg) {
    int pix = blockIdx.x * 256 + threadIdx.x;
    int b = blockIdx.y;
    const float* base = logits + (size_t)b * C_ * HW_ + pix;
    float v[C_];
    #pragma unroll
    for (int c = 0; c < C_; c++) v[c] = base[(size_t)c * HW_];
    float m = v[0]; int bi = 0;
    #pragma unroll
    for (int c = 1; c < C_; c++) if (v[c] > m) { m = v[c]; bi = c; }
    float s = 0.f;
    #pragma unroll
    for (int c = 0; c < C_; c++) s += expf(v[c] - m);
    int idx = b * HW_ + pix;
    o_seg[idx] = (float)bi;
    g_m[idx] = m;
    g_s[idx] = s;
}

// ---------------- K2: vote map (exact op order to match reference) ----------------
__global__ __launch_bounds__(256) void k_vote(const float* __restrict__ reg) {
    __shared__ float2 S[18][43];
    int b = blockIdx.z;
    int ox0 = blockIdx.x * 32, oy0 = blockIdx.y * 8;
    const float* r0 = reg + (size_t)b * 2 * HW_;
    const float* r1 = r0 + HW_;
    int tid = threadIdx.y * 32 + threadIdx.x;
    for (int t = tid; t < 18 * 42; t += 256) {
        int rr = t / 42, cc = t % 42;
        int gy = oy0 + rr - 5, gx = ox0 + cc - 5;
        float vx = 0.f, vy = 0.f;
        if (gy >= 0 && gy < H_ && gx >= 0 && gx < W_) {
            int q = gy * W_ + gx;
            vx = r0[q]; vy = r1[q];
        }
        S[rr][cc] = make_float2(vx, vy);
    }
    __syncthreads();
    int tx = threadIdx.x, ty = threadIdx.y;
    float acc = 0.f;
    #pragma unroll
    for (int i = 0; i < 11; i++) {
        #pragma unroll
        for (int j = 0; j < 11; j++) {
            const int di = i - 5, dj = j - 5;
            if (di*di + dj*dj <= 25) {   // cmask, compile-time
                float2 v = S[ty + i][tx + j];
                float dx = __fsub_rn((float)dj, v.x);
                float dy = __fsub_rn((float)di, v.y);
                float t2 = __fadd_rn(__fmul_rn(dx, dx), __fmul_rn(dy, dy));
                acc = __fadd_rn(acc, __fsqrt_rn(t2));
            }
        }
    }
    float t = __fdiv_rn(acc, 81.0f);
    float vote = __fadd_rn(-t, -1.0f);
    g_vote[b * HW_ + (oy0 + ty) * W_ + ox0 + tx] = vote;
}

// ---------------- K3: 7x7 max-pool + keep + center_map + candidate list ----------------
__global__ __launch_bounds__(256) void k_pool(float thrF, float* __restrict__ o_cmap) {
    __shared__ float T[14][39];
    int b = blockIdx.z;
    int ox0 = blockIdx.x * 32, oy0 = blockIdx.y * 8;
    int tid = threadIdx.y * 32 + threadIdx.x;
    for (int t = tid; t < 14 * 38; t += 256) {
        int rr = t / 38, cc = t % 38;
        int gy = oy0 + rr - 3, gx = ox0 + cc - 3;
        T[rr][cc] = (gy >= 0 && gy < H_ && gx >= 0 && gx < W_)
                    ? g_vote[b * HW_ + gy * W_ + gx] : -CUDART_INF_F;
    }
    __syncthreads();
    int tx = threadIdx.x, ty = threadIdx.y;
    float v = T[ty + 3][tx + 3];
    float m = -CUDART_INF_F;
    #pragma unroll
    for (int i = 0; i < 7; i++)
        #pragma unroll
        for (int j = 0; j < 7; j++)
            m = fmaxf(m, T[ty + i][tx + j]);
    bool keep = (m == v) && (v > thrF);
    int pix = (oy0 + ty) * W_ + ox0 + tx;
    o_cmap[b * HW_ + pix] = keep ? v : 0.f;
    if (keep) {
        int p = atomicAdd(&g_cnt[b], 1);
        if (p < MAXK_) { g_kval[b * MAXK_ + p] = v; g_kidx[b * MAXK_ + p] = pix; }
    }
}

// ---------------- K4a: chip-wide exact rank (value desc, index asc) ----------------
__global__ __launch_bounds__(256) void k_rank() {
    __shared__ float sv[MAXK_];
    __shared__ int   si[MAXK_];
    int b = blockIdx.y;
    int n = g_cnt[b];
    if (n > MAXK_) n = MAXK_;
    int tid = threadIdx.x;
    for (int i = tid; i < n; i += 256) {
        sv[i] = g_kval[b * MAXK_ + i];
        si[i] = g_kidx[b * MAXK_ + i];
    }
    __syncthreads();
    int i = blockIdx.x * 256 + tid;
    if (i >= n) return;
    float v = sv[i]; int id = si[i];
    int r = 0;
    int j = 0;
    for (; j + 4 <= n; j += 4) {
        float v0 = sv[j], v1 = sv[j+1], v2 = sv[j+2], v3 = sv[j+3];
        int i0 = si[j], i1 = si[j+1], i2 = si[j+2], i3 = si[j+3];
        r += (v0 > v) || (v0 == v && i0 < id);
        r += (v1 > v) || (v1 == v && i1 < id);
        r += (v2 > v) || (v2 == v && i2 < id);
        r += (v3 > v) || (v3 == v && i3 < id);
    }
    for (; j < n; j++)
        r += (sv[j] > v) || (sv[j] == v && si[j] < id);
    if (r < TOPK_) { g_tv[b * TOPK_ + r] = v; g_ti[b * TOPK_ + r] = id; }
}

// ---------------- K4b: -inf fill (rare) + centers/coeffs output ----------------
__global__ __launch_bounds__(256) void k_centers(const float* __restrict__ o_cmap,
                                                 float* __restrict__ o_cent,
                                                 float* __restrict__ o_tv) {
    int b = blockIdx.x;
    int tid = threadIdx.x;
    int n = g_cnt[b];
    if (n > MAXK_) n = MAXK_;
    if (tid == 0 && n < TOPK_) {
        // jax top_k pads with the lowest-index -inf entries (non-keep positions)
        const float* cm = o_cmap + (size_t)b * HW_;
        int slot = n;
        for (int idx = 0; idx < HW_ && slot < TOPK_; idx++) {
            if (cm[idx] == 0.f) {
                g_tv[b * TOPK_ + slot] = -CUDART_INF_F;
                g_ti[b * TOPK_ + slot] = idx;
                slot++;
            }
        }
    }
    __syncthreads();
    if (tid < TOPK_) {
        float v = g_tv[b * TOPK_ + tid];
        int id = g_ti[b * TOPK_ + tid];
        int ys = id / W_, xs = id % W_;
        o_cent[(b * TOPK_ + tid) * 2 + 0] = (float)ys;
        o_cent[(b * TOPK_ + tid) * 2 + 1] = (float)xs;
        o_tv[b * TOPK_ + tid] = v;
        bool valid = isfinite(v);
        float cx = valid ? (float)xs : 1e9f;
        float cy = valid ? (float)ys : 1e9f;
        g_ca[b * TOPK_ + tid] = -2.f * cx;
        g_cb[b * TOPK_ + tid] = -2.f * cy;
        g_cc[b * TOPK_ + tid] = cx * cx + cy * cy;
    }
}

// ---------------- K5a: classify things + compact list ----------------
__global__ __launch_bounds__(256) void k_things(const float* __restrict__ o_seg,
                                                float* __restrict__ o_inst) {
    int pix = blockIdx.x * 256 + threadIdx.x;
    int b = blockIdx.y;
    float s = o_seg[b * HW_ + pix];
    bool things = (s > 23.99f) && (s <= 33.0f);
    if (!things) o_inst[b * HW_ + pix] = 0.f;
    unsigned ball = __ballot_sync(0xffffffffu, things);
    if (ball == 0) return;
    int lane = threadIdx.x & 31;
    int leader = __ffs(ball) - 1;
    int prefix = __popc(ball & ((1u << lane) - 1u));
    int base = 0;
    if (lane == leader) base = atomicAdd(&g_tcnt[b], __popc(ball));
    base = __shfl_sync(0xffffffffu, base, leader);
    if (things) g_tlist[b * HW_ + base + prefix] = pix;
}

// ---------------- K5b: argmin over 200 centers (things only) + fused histogram ----------------
__global__ __launch_bounds__(256) void k_argmin(const float* __restrict__ reg,
                                                const float* __restrict__ o_seg,
                                                float* __restrict__ o_inst) {
    __shared__ float4 Ctr[TOPK_];
    int b = blockIdx.y;
    int tid = threadIdx.x;
    if (tid < TOPK_)
        Ctr[tid] = make_float4(g_ca[b * TOPK_ + tid], g_cb[b * TOPK_ + tid],
                               g_cc[b * TOPK_ + tid], 0.f);
    __syncthreads();
    int n = g_tcnt[b];
    int i = blockIdx.x * 256 + tid;
    int inst = 0, cls = 0;
    if (i < n) {
        int pix = g_tlist[b * HW_ + i];
        int y = pix >> 10, x = pix & 1023;
        const float* r0 = reg + (size_t)b * 2 * HW_;
        float px = (float)(x + 1) - r0[pix];
        float py = (float)(y + 1) - r0[HW_ + pix];
        float best = CUDART_INF_F; int bi = 0;
        #pragma unroll 10
        for (int k = 0; k < TOPK_; k++) {
            float4 c = Ctr[k];
            float t = __fmaf_rn(c.x, px, __fmaf_rn(c.y, py, c.z));
            if (t < best) { best = t; bi = k; }
        }
        o_inst[b * HW_ + pix] = (float)(bi + 1);
        inst = bi + 1;
        cls = (int)o_seg[b * HW_ + pix];
    }
    // warp-aggregated histogram atomics keyed on (inst, cls)
    int key = inst * 64 + cls;            // inst==0 -> no contribution
    unsigned peers = __match_any_sync(0xffffffffu, key);
    int lane = threadIdx.x & 31;
    int leader = __ffs(peers) - 1;
    if (inst > 0 && lane == leader)
        atomicAdd(&g_counts[(b * TOPK_ + inst - 1) * C_ + cls], __popc(peers));
}

// ---------------- K6: instance class (argmax) + size ----------------
__global__ void k_class(float* __restrict__ o_cls, float* __restrict__ o_size) {
    int t = threadIdx.x;
    int b = blockIdx.x;
    const int* base = &g_counts[(b * TOPK_ + t) * C_];
    int sum = 0, best = -1, bi = 0;
    #pragma unroll
    for (int c = 0; c < C_; c++) {
        int cnt = base[c];
        sum += cnt;
        if (cnt > best) { best = cnt; bi = c; }
    }
    o_cls[b * TOPK_ + t]  = (float)bi;
    o_size[b * TOPK_ + t] = (float)sum;
    g_cls[b * TOPK_ + t]  = bi;
}

// ---------------- K7: per-instance prob sums over compacted list ----------------
__global__ __launch_bounds__(256) void k_prob(const float* __restrict__ logits,
                                              const float* __restrict__ o_inst) {
    int b = blockIdx.y;
    int n = g_tcnt[b];
    int i = blockIdx.x * 256 + threadIdx.x;
    int inst = 0;
    float p = 0.f;
    if (i < n) {
        int pix = g_tlist[b * HW_ + i];
        int idx = b * HW_ + pix;
        inst = (int)o_inst[idx];
        int c = g_cls[b * TOPK_ + inst - 1];
        float l = logits[((size_t)b * C_ + c) * HW_ + pix];
        p = expf(l - g_m[idx]) / g_s[idx];
    }
    unsigned peers = __match_any_sync(0xffffffffu, inst);
    int lane = threadIdx.x & 31;
    int leader = __ffs(peers) - 1;
    float tot = 0.f;
    #pragma unroll
    for (int k = 0; k < 32; k++) {
        float pk = __shfl_sync(0xffffffffu, p, k);
        if (peers & (1u << k)) tot += pk;
    }
    if (inst > 0 && lane == leader)
        atomicAdd(&g_psum[b * TOPK_ + inst - 1], tot);
}

// ---------------- K8: finalize inst_seg_prob ----------------
__global__ void k_fin(const float* __restrict__ o_size, float* __restrict__ o_prob) {
    int t = blockIdx.x * blockDim.x + threadIdx.x;
    if (t < B_ * TOPK_)
        o_prob[t] = g_psum[t] / fmaxf(o_size[t], 1.f);
}

// ---------------- host ----------------
extern "C" void kernel_launch(void* const* d_in, const int* in_sizes, int n_in,
                              void* d_out, int out_size) {
    const float* logits = (const float*)d_in[0];
    const float* regs   = (const float*)d_in[2];
    float* out = (float*)d_out;

    float* o_inst = out;                    // [B, H, W]
    float* o_seg  = out + 2 * HW_;          // [B, H, W]
    float* o_cent = out + 4 * HW_;          // [B, 200, 2]
    float* o_tv   = o_cent + B_ * TOPK_ * 2;// [B, 200]
    float* o_cls  = o_tv   + B_ * TOPK_;    // [B, 200]
    float* o_prob = o_cls  + B_ * TOPK_;    // [B, 200]
    float* o_size = o_prob + B_ * TOPK_;    // [B, 200]
    float* o_cmap = o_size + B_ * TOPK_;    // [B, H, W]

    // Threshold: numpy float32 pairwise sum of (cd*cmask) over 11x11,
    // thr = double(sum)/81.0, compare value = float(-thr - 1.0)
    float a[121];
    for (int i = 0; i < 11; i++)
        for (int j = 0; j < 11; j++) {
            int di = i - 5, dj = j - 5;
            int r2 = di * di + dj * dj;
            a[i * 11 + j] = (r2 <= 25) ? sqrtf((float)r2) : 0.0f;
        }
    float r[8];
    for (int k = 0; k < 8; k++) r[k] = a[k];
    int i = 8;
    for (; i < 120; i += 8)
        for (int k = 0; k < 8; k++) r[k] += a[i + k];
    float res = ((r[0] + r[1]) + (r[2] + r[3])) + ((r[4] + r[5]) + (r[6] + r[7]));
    for (; i < 121; i++) res += a[i];
    double thr = (double)res / 81.0;
    float thrF = (float)(-thr - 1.0);

    const int RBLK = (MAXK_ + 255) / 256;   // 23
    k_init<<<1, 1024>>>();
    k_seg<<<dim3(HW_ / 256, B_), 256>>>(logits, o_seg);
    k_vote<<<dim3(W_ / 32, H_ / 8, B_), dim3(32, 8)>>>(regs);
    k_pool<<<dim3(W_ / 32, H_ / 8, B_), dim3(32, 8)>>>(thrF, o_cmap);
    k_rank<<<dim3(RBLK, B_), 256>>>();
    k_centers<<<B_, 256>>>(o_cmap, o_cent, o_tv);
    k_things<<<dim3(HW_ / 256, B_), 256>>>(o_seg, o_inst);
    k_argmin<<<dim3(HW_ / 256, B_), 256>>>(regs, o_seg, o_inst);
    k_class<<<B_, TOPK_>>>(o_cls, o_size);
    k_prob<<<dim3(HW_ / 256, B_), 256>>>(logits, o_inst);
    k_fin<<<1, 512>>>(o_size, o_prob);
}